// round 11
// baseline (speedup 1.0000x reference)
#include <cuda_runtime.h>
#include <math.h>
#include <stdint.h>

// Problem constants
#define BATCH 4
#define SEQ   2048
#define DIMI  768
#define EMB   512
#define HEADS 8
#define HD    64
#define MROWS (BATCH*SEQ)   // 8192

// Scratch (allocation-free: __device__ globals)
__device__ float g_Q[MROWS*EMB];
__device__ float g_K[MROWS*EMB];
__device__ float g_V[MROWS*EMB];
__device__ float g_C[MROWS*EMB];

// ---------------------------------------------------------------------------
// TF32 helpers
// ---------------------------------------------------------------------------
__device__ __forceinline__ uint32_t f2tf(float x) {
    uint32_t r;
    asm("cvt.rna.tf32.f32 %0, %1;" : "=r"(r) : "f"(x));
    return r;
}

__device__ __forceinline__ float ex2(float x) {
    float y;
    asm("ex2.approx.f32 %0, %1;" : "=f"(y) : "f"(x));
    return y;
}

// D = A(16x8, tf32) * B(8x8, tf32) + D  (fp32 accum)
__device__ __forceinline__ void mma_tf32(float c[4], const uint32_t a[4],
                                         uint32_t b0, uint32_t b1) {
    asm volatile(
        "mma.sync.aligned.m16n8k8.row.col.f32.tf32.tf32.f32 "
        "{%0,%1,%2,%3}, {%4,%5,%6,%7}, {%8,%9}, {%0,%1,%2,%3};\n"
        : "+f"(c[0]), "+f"(c[1]), "+f"(c[2]), "+f"(c[3])
        : "r"(a[0]), "r"(a[1]), "r"(a[2]), "r"(a[3]), "r"(b0), "r"(b1));
}

// ---------------------------------------------------------------------------
// TF32 tensor-core GEMM + bias (unchanged from round 4 — control group)
// ---------------------------------------------------------------------------
#define PADA 20
#define PADB 136

__global__ __launch_bounds__(256, 2)
void gemm_tf32(const float* __restrict__ A, const float* __restrict__ W,
               const float* __restrict__ bias, float* __restrict__ C,
               int M, int N, int K)
{
    __shared__ uint32_t As[128 * PADA];
    __shared__ uint32_t Bs[16 * PADB];

    const int tid  = threadIdx.x;
    const int lane = tid & 31, w = tid >> 5;
    const int g = lane >> 2, t = lane & 3;
    const int wm = (w >> 2) * 64, wn = (w & 3) * 32;
    const int m0 = blockIdx.y * 128, n0 = blockIdx.x * 128;

    float acc[4][4][4];
    #pragma unroll
    for (int mt = 0; mt < 4; mt++)
        #pragma unroll
        for (int nt = 0; nt < 4; nt++)
            #pragma unroll
            for (int c = 0; c < 4; c++) acc[mt][nt][c] = 0.f;

    for (int k0 = 0; k0 < K; k0 += 16) {
        #pragma unroll
        for (int it = 0; it < 2; it++) {
            int idx = tid + it * 256;
            int m = idx >> 2, cq = idx & 3;
            float4 v = *(const float4*)(A + (size_t)(m0 + m) * K + k0 + cq * 4);
            uint32_t* p = &As[m * PADA + cq * 4];
            p[0] = f2tf(v.x); p[1] = f2tf(v.y); p[2] = f2tf(v.z); p[3] = f2tf(v.w);
        }
        #pragma unroll
        for (int it = 0; it < 2; it++) {
            int idx = tid + it * 256;
            int kr = idx >> 5, n4 = idx & 31;
            float4 v = *(const float4*)(W + (size_t)(k0 + kr) * N + n0 + n4 * 4);
            uint32_t* p = &Bs[kr * PADB + n4 * 4];
            p[0] = f2tf(v.x); p[1] = f2tf(v.y); p[2] = f2tf(v.z); p[3] = f2tf(v.w);
        }
        __syncthreads();

        #pragma unroll
        for (int ks = 0; ks < 2; ks++) {
            uint32_t a[4][4], b[4][2];
            #pragma unroll
            for (int mt = 0; mt < 4; mt++) {
                int r = wm + mt * 16;
                a[mt][0] = As[(r + g)     * PADA + ks * 8 + t];
                a[mt][1] = As[(r + g + 8) * PADA + ks * 8 + t];
                a[mt][2] = As[(r + g)     * PADA + ks * 8 + t + 4];
                a[mt][3] = As[(r + g + 8) * PADA + ks * 8 + t + 4];
            }
            #pragma unroll
            for (int nt = 0; nt < 4; nt++) {
                int c = wn + nt * 8 + g;
                b[nt][0] = Bs[(ks * 8 + t)     * PADB + c];
                b[nt][1] = Bs[(ks * 8 + t + 4) * PADB + c];
            }
            #pragma unroll
            for (int mt = 0; mt < 4; mt++)
                #pragma unroll
                for (int nt = 0; nt < 4; nt++)
                    mma_tf32(acc[mt][nt], a[mt], b[nt][0], b[nt][1]);
        }
        __syncthreads();
    }

    #pragma unroll
    for (int nt = 0; nt < 4; nt++) {
        int col = n0 + wn + nt * 8 + 2 * t;
        float2 bb = *(const float2*)(bias + col);
        #pragma unroll
        for (int mt = 0; mt < 4; mt++) {
            int r = m0 + wm + mt * 16 + g;
            *(float2*)(C + (size_t)r * N + col) =
                make_float2(acc[mt][nt][0] + bb.x, acc[mt][nt][1] + bb.y);
            *(float2*)(C + (size_t)(r + 8) * N + col) =
                make_float2(acc[mt][nt][2] + bb.x, acc[mt][nt][3] + bb.y);
        }
    }
}

// ---------------------------------------------------------------------------
// TF32 flash attention v3: BM=128, 4 warps, 32 q-rows (2 m16) per warp.
//  - P transpose via warp shuffles (no P SMEM round trip)
//  - register-prefetch pipeline: K(t+1) loads overlap S(t), V(t+1) overlaps PV(t)
//  - exp2-domain softmax (log2e folded into Q scale)
// K/V in swizzled class-grouped SMEM:
//   word(r,n) = r*64 + (((n&7) ^ 2*(r&3)) + 8*(n>>5))*4 + ((n>>3)&3)
// ---------------------------------------------------------------------------
#define QP 68   // Qs [q][d]: a-load banks 4g+t distinct -> conflict-free

__device__ __forceinline__ int kvw(int r, int n) {
    return (r << 6) + ((((n & 7) ^ ((r & 3) << 1)) + ((n >> 5) << 3)) << 2)
                    + ((n >> 3) & 3);
}

__global__ __launch_bounds__(128, 2)
void flash_tf32(const float* __restrict__ Qg, const float* __restrict__ Kg,
                const float* __restrict__ Vg, float* __restrict__ Og)
{
    extern __shared__ uint32_t smx[];
    uint32_t* Qs = smx;                 // [128][QP]
    uint32_t* Ks = Qs + 128 * QP;       // [64*64] swizzled (dim rows, key cols)
    uint32_t* Vs = Ks + 64 * 64;        // [64*64] swizzled (key rows, dim cols)

    const int tid  = threadIdx.x;
    const int lane = tid & 31, w = tid >> 5;
    const int g = lane >> 2, t = lane & 3;
    const int wq = w * 32;
    const int q0 = blockIdx.x * 128;
    const int bh = blockIdx.y, b = bh >> 3, h = bh & 7;
    const size_t base = (size_t)b * SEQ * EMB + (size_t)h * HD;
    const float qscale = 0.125f * 1.44269504089f;   // 1/sqrt(64) * log2(e)

    // K loader mapping: key = idx&63, dq = idx>>6 (transposed store)
    // V loader mapping: key = idx>>4, dq = idx&15 (coalesced)
    float4 kr[8], vr[8];

    // Load Q tile once (pre-scaled into exp2 domain, tf32).
    #pragma unroll
    for (int it = 0; it < 16; it++) {
        int idx = tid + it * 128;
        int m = idx >> 4, dq = idx & 15;
        float4 v = *(const float4*)(Qg + base + (size_t)(q0 + m) * EMB + dq * 4);
        uint32_t* p = &Qs[m * QP + dq * 4];
        p[0] = f2tf(v.x * qscale); p[1] = f2tf(v.y * qscale);
        p[2] = f2tf(v.z * qscale); p[3] = f2tf(v.w * qscale);
    }

    // Preload tile 0.
    #pragma unroll
    for (int it = 0; it < 8; it++) {
        int idx = tid + it * 128;
        int key = idx & 63, dq = idx >> 6;
        kr[it] = *(const float4*)(Kg + base + (size_t)key * EMB + dq * 4);
    }
    #pragma unroll
    for (int it = 0; it < 8; it++) {
        int idx = tid + it * 128;
        int key = idx & 63, dq = idx >> 6;
        Ks[kvw(dq * 4 + 0, key)] = f2tf(kr[it].x);
        Ks[kvw(dq * 4 + 1, key)] = f2tf(kr[it].y);
        Ks[kvw(dq * 4 + 2, key)] = f2tf(kr[it].z);
        Ks[kvw(dq * 4 + 3, key)] = f2tf(kr[it].w);
    }
    #pragma unroll
    for (int it = 0; it < 8; it++) {
        int idx = tid + it * 128;
        int key = idx >> 4, dq = idx & 15;
        vr[it] = *(const float4*)(Vg + base + (size_t)key * EMB + dq * 4);
    }
    #pragma unroll
    for (int it = 0; it < 8; it++) {
        int idx = tid + it * 128;
        int key = idx >> 4, dq = idx & 15;
        Vs[kvw(key, dq * 4 + 0)] = f2tf(vr[it].x);
        Vs[kvw(key, dq * 4 + 1)] = f2tf(vr[it].y);
        Vs[kvw(key, dq * 4 + 2)] = f2tf(vr[it].z);
        Vs[kvw(key, dq * 4 + 3)] = f2tf(vr[it].w);
    }
    __syncthreads();

    float m_i[2][2], l_i[2][2];
    float o[2][8][4];
    #pragma unroll
    for (int mt = 0; mt < 2; mt++) {
        m_i[mt][0] = m_i[mt][1] = -1e30f;
        l_i[mt][0] = l_i[mt][1] = 0.f;
        #pragma unroll
        for (int nt = 0; nt < 8; nt++)
            #pragma unroll
            for (int c = 0; c < 4; c++) o[mt][nt][c] = 0.f;
    }

    for (int kt = 0; kt < SEQ / 64; kt++) {
        const bool pf = (kt + 1 < SEQ / 64);
        // Prefetch K(kt+1) into registers (overlaps S-compute).
        if (pf) {
            const size_t kb = base + (size_t)((kt + 1) * 64) * EMB;
            #pragma unroll
            for (int it = 0; it < 8; it++) {
                int idx = tid + it * 128;
                int key = idx & 63, dq = idx >> 6;
                kr[it] = *(const float4*)(Kg + kb + (size_t)key * EMB + dq * 4);
            }
        }

        // ---- S = Q K^T ----
        float s[2][8][4];
        #pragma unroll
        for (int mt = 0; mt < 2; mt++)
            #pragma unroll
            for (int nt = 0; nt < 8; nt++)
                #pragma unroll
                for (int c = 0; c < 4; c++) s[mt][nt][c] = 0.f;

        #pragma unroll
        for (int ks = 0; ks < 8; ks++) {
            const int r0 = ks * 8 + t, r1 = r0 + 4;
            const int sw = (g ^ (t << 1)) << 2;
            uint32_t kb0[8], kb1[8];
            {
                uint4 x = *(const uint4*)(Ks + (r0 << 6) + sw);
                kb0[0] = x.x; kb0[1] = x.y; kb0[2] = x.z; kb0[3] = x.w;
                uint4 y = *(const uint4*)(Ks + (r0 << 6) + sw + 32);
                kb0[4] = y.x; kb0[5] = y.y; kb0[6] = y.z; kb0[7] = y.w;
                uint4 z = *(const uint4*)(Ks + (r1 << 6) + sw);
                kb1[0] = z.x; kb1[1] = z.y; kb1[2] = z.z; kb1[3] = z.w;
                uint4 u = *(const uint4*)(Ks + (r1 << 6) + sw + 32);
                kb1[4] = u.x; kb1[5] = u.y; kb1[6] = u.z; kb1[7] = u.w;
            }
            #pragma unroll
            for (int mt = 0; mt < 2; mt++) {
                const int R = wq + mt * 16;
                uint32_t a[4];
                a[0] = Qs[(R + g)     * QP + ks * 8 + t];
                a[1] = Qs[(R + g + 8) * QP + ks * 8 + t];
                a[2] = Qs[(R + g)     * QP + ks * 8 + t + 4];
                a[3] = Qs[(R + g + 8) * QP + ks * 8 + t + 4];
                #pragma unroll
                for (int nt = 0; nt < 8; nt++)
                    mma_tf32(s[mt][nt], a, kb0[nt], kb1[nt]);
            }
        }

        // ---- online softmax (exp2 domain); converts s in-place to tf32 bits ----
        #pragma unroll
        for (int mt = 0; mt < 2; mt++) {
            #pragma unroll
            for (int hr = 0; hr < 2; hr++) {
                float rmax = -1e30f;
                #pragma unroll
                for (int nt = 0; nt < 8; nt++)
                    rmax = fmaxf(rmax, fmaxf(s[mt][nt][2 * hr], s[mt][nt][2 * hr + 1]));
                rmax = fmaxf(rmax, __shfl_xor_sync(0xffffffffu, rmax, 1));
                rmax = fmaxf(rmax, __shfl_xor_sync(0xffffffffu, rmax, 2));
                float mnew  = fmaxf(m_i[mt][hr], rmax);
                float alpha = ex2(m_i[mt][hr] - mnew);
                float rsum = 0.f;
                #pragma unroll
                for (int nt = 0; nt < 8; nt++) {
                    float p0 = ex2(s[mt][nt][2 * hr]     - mnew);
                    float p1 = ex2(s[mt][nt][2 * hr + 1] - mnew);
                    rsum += p0 + p1;
                    s[mt][nt][2 * hr]     = __uint_as_float(f2tf(p0));
                    s[mt][nt][2 * hr + 1] = __uint_as_float(f2tf(p1));
                }
                rsum += __shfl_xor_sync(0xffffffffu, rsum, 1);
                rsum += __shfl_xor_sync(0xffffffffu, rsum, 2);
                l_i[mt][hr] = l_i[mt][hr] * alpha + rsum;
                m_i[mt][hr] = mnew;
                #pragma unroll
                for (int nt = 0; nt < 8; nt++) {
                    o[mt][nt][2 * hr]     *= alpha;
                    o[mt][nt][2 * hr + 1] *= alpha;
                }
            }
        }

        __syncthreads();   // all warps done reading Ks(kt)

        // Store prefetched K(kt+1); prefetch V(kt+1) (overlaps PV).
        if (pf) {
            #pragma unroll
            for (int it = 0; it < 8; it++) {
                int idx = tid + it * 128;
                int key = idx & 63, dq = idx >> 6;
                Ks[kvw(dq * 4 + 0, key)] = f2tf(kr[it].x);
                Ks[kvw(dq * 4 + 1, key)] = f2tf(kr[it].y);
                Ks[kvw(dq * 4 + 2, key)] = f2tf(kr[it].z);
                Ks[kvw(dq * 4 + 3, key)] = f2tf(kr[it].w);
            }
            const size_t vb = base + (size_t)((kt + 1) * 64) * EMB;
            #pragma unroll
            for (int it = 0; it < 8; it++) {
                int idx = tid + it * 128;
                int key = idx >> 4, dq = idx & 15;
                vr[it] = *(const float4*)(Vg + vb + (size_t)key * EMB + dq * 4);
            }
        }

        // ---- O += P V (P a-frags via warp shuffle of s) ----
        const int srcA = (lane & ~3) | (t >> 1);   // 4g + t/2
        const int srcB = srcA + 2;
        const bool odd = (t & 1);
        #pragma unroll
        for (int ks = 0; ks < 8; ks++) {
            const int r0 = ks * 8 + t, r1 = r0 + 4;
            const int sw = (g ^ (t << 1)) << 2;
            uint32_t vb0[8], vb1[8];
            {
                uint4 x = *(const uint4*)(Vs + (r0 << 6) + sw);
                vb0[0] = x.x; vb0[1] = x.y; vb0[2] = x.z; vb0[3] = x.w;
                uint4 y = *(const uint4*)(Vs + (r0 << 6) + sw + 32);
                vb0[4] = y.x; vb0[5] = y.y; vb0[6] = y.z; vb0[7] = y.w;
                uint4 z = *(const uint4*)(Vs + (r1 << 6) + sw);
                vb1[0] = z.x; vb1[1] = z.y; vb1[2] = z.z; vb1[3] = z.w;
                uint4 u = *(const uint4*)(Vs + (r1 << 6) + sw + 32);
                vb1[4] = u.x; vb1[5] = u.y; vb1[6] = u.z; vb1[7] = u.w;
            }
            #pragma unroll
            for (int mt = 0; mt < 2; mt++) {
                float w0 = __shfl_sync(0xffffffffu, s[mt][ks][0], srcA);
                float w1 = __shfl_sync(0xffffffffu, s[mt][ks][1], srcA);
                float w2 = __shfl_sync(0xffffffffu, s[mt][ks][2], srcA);
                float w3 = __shfl_sync(0xffffffffu, s[mt][ks][3], srcA);
                float x0 = __shfl_sync(0xffffffffu, s[mt][ks][0], srcB);
                float x1 = __shfl_sync(0xffffffffu, s[mt][ks][1], srcB);
                float x2 = __shfl_sync(0xffffffffu, s[mt][ks][2], srcB);
                float x3 = __shfl_sync(0xffffffffu, s[mt][ks][3], srcB);
                uint32_t a[4];
                a[0] = __float_as_uint(odd ? w1 : w0);
                a[1] = __float_as_uint(odd ? w3 : w2);
                a[2] = __float_as_uint(odd ? x1 : x0);
                a[3] = __float_as_uint(odd ? x3 : x2);
                #pragma unroll
                for (int nt = 0; nt < 8; nt++)
                    mma_tf32(o[mt][nt], a, vb0[nt], vb1[nt]);
            }
        }

        __syncthreads();   // all warps done reading Vs(kt)

        if (pf) {
            #pragma unroll
            for (int it = 0; it < 8; it++) {
                int idx = tid + it * 128;
                int key = idx >> 4, dq = idx & 15;
                Vs[kvw(key, dq * 4 + 0)] = f2tf(vr[it].x);
                Vs[kvw(key, dq * 4 + 1)] = f2tf(vr[it].y);
                Vs[kvw(key, dq * 4 + 2)] = f2tf(vr[it].z);
                Vs[kvw(key, dq * 4 + 3)] = f2tf(vr[it].w);
            }
        }
        // V(kt+1) STS is ordered before PV(kt+1) by the next iteration's
        // first __syncthreads(); K(kt+1) STS before S(kt+1) by the second.
    }

    // Normalize + write context in [B, S, H*Dh] layout.
    #pragma unroll
    for (int mt = 0; mt < 2; mt++) {
        float inv0 = __fdividef(1.f, l_i[mt][0]);
        float inv1 = __fdividef(1.f, l_i[mt][1]);
        const int R = q0 + wq + mt * 16;
        #pragma unroll
        for (int nt = 0; nt < 8; nt++) {
            size_t r0 = base + (size_t)(R + g) * EMB + nt * 8 + 2 * t;
            *(float2*)(Og + r0) = make_float2(o[mt][nt][0] * inv0, o[mt][nt][1] * inv0);
            size_t r1 = base + (size_t)(R + g + 8) * EMB + nt * 8 + 2 * t;
            *(float2*)(Og + r1) = make_float2(o[mt][nt][2] * inv1, o[mt][nt][3] * inv1);
        }
    }
}

// ---------------------------------------------------------------------------
extern "C" void kernel_launch(void* const* d_in, const int* in_sizes, int n_in,
                              void* d_out, int out_size)
{
    const float* q  = (const float*)d_in[0];
    const float* k  = (const float*)d_in[1];
    const float* v  = (const float*)d_in[2];
    const float* wq = (const float*)d_in[3];
    const float* bq = (const float*)d_in[4];
    const float* wk = (const float*)d_in[5];
    const float* bk = (const float*)d_in[6];
    const float* wv = (const float*)d_in[7];
    const float* bv = (const float*)d_in[8];
    const float* wo = (const float*)d_in[9];
    const float* bo = (const float*)d_in[10];
    float* out = (float*)d_out;

    float *Qb, *Kb, *Vb, *Cb;
    cudaGetSymbolAddress((void**)&Qb, g_Q);
    cudaGetSymbolAddress((void**)&Kb, g_K);
    cudaGetSymbolAddress((void**)&Vb, g_V);
    cudaGetSymbolAddress((void**)&Cb, g_C);

    // QKV projections: [8192,768] @ [768,512] + bias
    dim3 gp(EMB / 128, MROWS / 128);
    gemm_tf32<<<gp, 256>>>(q, wq, bq, Qb, MROWS, EMB, DIMI);
    gemm_tf32<<<gp, 256>>>(k, wk, bk, Kb, MROWS, EMB, DIMI);
    gemm_tf32<<<gp, 256>>>(v, wv, bv, Vb, MROWS, EMB, DIMI);

    // Flash attention: grid (S/128, B*H)
    int smem = (128 * QP + 64 * 64 * 2) * (int)sizeof(uint32_t);  // 67584 B
    cudaFuncSetAttribute(flash_tf32, cudaFuncAttributeMaxDynamicSharedMemorySize, smem);
    flash_tf32<<<dim3(SEQ / 128, BATCH * HEADS), 128, smem>>>(Qb, Kb, Vb, Cb);

    // Output projection: [8192,512] @ [512,768] + bias -> d_out
    dim3 go(DIMI / 128, MROWS / 128);
    gemm_tf32<<<go, 256>>>(Cb, wo, bo, out, MROWS, DIMI, EMB);
}

// round 12
// speedup vs baseline: 1.0045x; 1.0045x over previous
#include <cuda_runtime.h>
#include <math.h>
#include <stdint.h>

// Problem constants
#define BATCH 4
#define SEQ   2048
#define DIMI  768
#define EMB   512
#define HEADS 8
#define HD    64
#define MROWS (BATCH*SEQ)   // 8192

// Scratch (allocation-free: __device__ globals)
__device__ float g_Q[MROWS*EMB];
__device__ float g_K[MROWS*EMB];
__device__ float g_V[MROWS*EMB];
__device__ float g_C[MROWS*EMB];

// ---------------------------------------------------------------------------
// TF32 helpers
// ---------------------------------------------------------------------------
__device__ __forceinline__ uint32_t f2tf(float x) {
    uint32_t r;
    asm("cvt.rna.tf32.f32 %0, %1;" : "=r"(r) : "f"(x));
    return r;
}

__device__ __forceinline__ float ex2(float x) {
    float y;
    asm("ex2.approx.f32 %0, %1;" : "=f"(y) : "f"(x));
    return y;
}

// D = A(16x8, tf32) * B(8x8, tf32) + D  (fp32 accum)
__device__ __forceinline__ void mma_tf32(float c[4], const uint32_t a[4],
                                         uint32_t b0, uint32_t b1) {
    asm volatile(
        "mma.sync.aligned.m16n8k8.row.col.f32.tf32.tf32.f32 "
        "{%0,%1,%2,%3}, {%4,%5,%6,%7}, {%8,%9}, {%0,%1,%2,%3};\n"
        : "+f"(c[0]), "+f"(c[1]), "+f"(c[2]), "+f"(c[3])
        : "r"(a[0]), "r"(a[1]), "r"(a[2]), "r"(a[3]), "r"(b0), "r"(b1));
}

// ---------------------------------------------------------------------------
// TF32 tensor-core GEMM + bias (unchanged from round 4 — control group)
// ---------------------------------------------------------------------------
#define PADA 20
#define PADB 136

__global__ __launch_bounds__(256, 2)
void gemm_tf32(const float* __restrict__ A, const float* __restrict__ W,
               const float* __restrict__ bias, float* __restrict__ C,
               int M, int N, int K)
{
    __shared__ uint32_t As[128 * PADA];
    __shared__ uint32_t Bs[16 * PADB];

    const int tid  = threadIdx.x;
    const int lane = tid & 31, w = tid >> 5;
    const int g = lane >> 2, t = lane & 3;
    const int wm = (w >> 2) * 64, wn = (w & 3) * 32;
    const int m0 = blockIdx.y * 128, n0 = blockIdx.x * 128;

    float acc[4][4][4];
    #pragma unroll
    for (int mt = 0; mt < 4; mt++)
        #pragma unroll
        for (int nt = 0; nt < 4; nt++)
            #pragma unroll
            for (int c = 0; c < 4; c++) acc[mt][nt][c] = 0.f;

    for (int k0 = 0; k0 < K; k0 += 16) {
        #pragma unroll
        for (int it = 0; it < 2; it++) {
            int idx = tid + it * 256;
            int m = idx >> 2, cq = idx & 3;
            float4 v = *(const float4*)(A + (size_t)(m0 + m) * K + k0 + cq * 4);
            uint32_t* p = &As[m * PADA + cq * 4];
            p[0] = f2tf(v.x); p[1] = f2tf(v.y); p[2] = f2tf(v.z); p[3] = f2tf(v.w);
        }
        #pragma unroll
        for (int it = 0; it < 2; it++) {
            int idx = tid + it * 256;
            int kr = idx >> 5, n4 = idx & 31;
            float4 v = *(const float4*)(W + (size_t)(k0 + kr) * N + n0 + n4 * 4);
            uint32_t* p = &Bs[kr * PADB + n4 * 4];
            p[0] = f2tf(v.x); p[1] = f2tf(v.y); p[2] = f2tf(v.z); p[3] = f2tf(v.w);
        }
        __syncthreads();

        #pragma unroll
        for (int ks = 0; ks < 2; ks++) {
            uint32_t a[4][4], b[4][2];
            #pragma unroll
            for (int mt = 0; mt < 4; mt++) {
                int r = wm + mt * 16;
                a[mt][0] = As[(r + g)     * PADA + ks * 8 + t];
                a[mt][1] = As[(r + g + 8) * PADA + ks * 8 + t];
                a[mt][2] = As[(r + g)     * PADA + ks * 8 + t + 4];
                a[mt][3] = As[(r + g + 8) * PADA + ks * 8 + t + 4];
            }
            #pragma unroll
            for (int nt = 0; nt < 4; nt++) {
                int c = wn + nt * 8 + g;
                b[nt][0] = Bs[(ks * 8 + t)     * PADB + c];
                b[nt][1] = Bs[(ks * 8 + t + 4) * PADB + c];
            }
            #pragma unroll
            for (int mt = 0; mt < 4; mt++)
                #pragma unroll
                for (int nt = 0; nt < 4; nt++)
                    mma_tf32(acc[mt][nt], a[mt], b[nt][0], b[nt][1]);
        }
        __syncthreads();
    }

    #pragma unroll
    for (int nt = 0; nt < 4; nt++) {
        int col = n0 + wn + nt * 8 + 2 * t;
        float2 bb = *(const float2*)(bias + col);
        #pragma unroll
        for (int mt = 0; mt < 4; mt++) {
            int r = m0 + wm + mt * 16 + g;
            *(float2*)(C + (size_t)r * N + col) =
                make_float2(acc[mt][nt][0] + bb.x, acc[mt][nt][1] + bb.y);
            *(float2*)(C + (size_t)(r + 8) * N + col) =
                make_float2(acc[mt][nt][2] + bb.x, acc[mt][nt][3] + bb.y);
        }
    }
}

// ---------------------------------------------------------------------------
// TF32 flash attention v3: BM=128, 4 warps, 32 q-rows (2 m16) per warp.
//  - P transpose via warp shuffles (no P SMEM round trip)
//  - register-prefetch pipeline: K(t+1) loads overlap S(t), V(t+1) overlaps PV(t)
//  - exp2-domain softmax (log2e folded into Q scale)
// K/V in swizzled class-grouped SMEM:
//   word(r,n) = r*64 + (((n&7) ^ 2*(r&3)) + 8*(n>>5))*4 + ((n>>3)&3)
// ---------------------------------------------------------------------------
#define QP 68   // Qs [q][d]: a-load banks 4g+t distinct -> conflict-free

__device__ __forceinline__ int kvw(int r, int n) {
    return (r << 6) + ((((n & 7) ^ ((r & 3) << 1)) + ((n >> 5) << 3)) << 2)
                    + ((n >> 3) & 3);
}

__global__ __launch_bounds__(128, 2)
void flash_tf32(const float* __restrict__ Qg, const float* __restrict__ Kg,
                const float* __restrict__ Vg, float* __restrict__ Og)
{
    extern __shared__ uint32_t smx[];
    uint32_t* Qs = smx;                 // [128][QP]
    uint32_t* Ks = Qs + 128 * QP;       // [64*64] swizzled (dim rows, key cols)
    uint32_t* Vs = Ks + 64 * 64;        // [64*64] swizzled (key rows, dim cols)

    const int tid  = threadIdx.x;
    const int lane = tid & 31, w = tid >> 5;
    const int g = lane >> 2, t = lane & 3;
    const int wq = w * 32;
    const int q0 = blockIdx.x * 128;
    const int bh = blockIdx.y, b = bh >> 3, h = bh & 7;
    const size_t base = (size_t)b * SEQ * EMB + (size_t)h * HD;
    const float qscale = 0.125f * 1.44269504089f;   // 1/sqrt(64) * log2(e)

    // K loader mapping: key = idx&63, dq = idx>>6 (transposed store)
    // V loader mapping: key = idx>>4, dq = idx&15 (coalesced)
    float4 kr[8], vr[8];

    // Load Q tile once (pre-scaled into exp2 domain, tf32).
    #pragma unroll
    for (int it = 0; it < 16; it++) {
        int idx = tid + it * 128;
        int m = idx >> 4, dq = idx & 15;
        float4 v = *(const float4*)(Qg + base + (size_t)(q0 + m) * EMB + dq * 4);
        uint32_t* p = &Qs[m * QP + dq * 4];
        p[0] = f2tf(v.x * qscale); p[1] = f2tf(v.y * qscale);
        p[2] = f2tf(v.z * qscale); p[3] = f2tf(v.w * qscale);
    }

    // Preload tile 0.
    #pragma unroll
    for (int it = 0; it < 8; it++) {
        int idx = tid + it * 128;
        int key = idx & 63, dq = idx >> 6;
        kr[it] = *(const float4*)(Kg + base + (size_t)key * EMB + dq * 4);
    }
    #pragma unroll
    for (int it = 0; it < 8; it++) {
        int idx = tid + it * 128;
        int key = idx & 63, dq = idx >> 6;
        Ks[kvw(dq * 4 + 0, key)] = f2tf(kr[it].x);
        Ks[kvw(dq * 4 + 1, key)] = f2tf(kr[it].y);
        Ks[kvw(dq * 4 + 2, key)] = f2tf(kr[it].z);
        Ks[kvw(dq * 4 + 3, key)] = f2tf(kr[it].w);
    }
    #pragma unroll
    for (int it = 0; it < 8; it++) {
        int idx = tid + it * 128;
        int key = idx >> 4, dq = idx & 15;
        vr[it] = *(const float4*)(Vg + base + (size_t)key * EMB + dq * 4);
    }
    #pragma unroll
    for (int it = 0; it < 8; it++) {
        int idx = tid + it * 128;
        int key = idx >> 4, dq = idx & 15;
        Vs[kvw(key, dq * 4 + 0)] = f2tf(vr[it].x);
        Vs[kvw(key, dq * 4 + 1)] = f2tf(vr[it].y);
        Vs[kvw(key, dq * 4 + 2)] = f2tf(vr[it].z);
        Vs[kvw(key, dq * 4 + 3)] = f2tf(vr[it].w);
    }
    __syncthreads();

    float m_i[2][2], l_i[2][2];
    float o[2][8][4];
    #pragma unroll
    for (int mt = 0; mt < 2; mt++) {
        m_i[mt][0] = m_i[mt][1] = -1e30f;
        l_i[mt][0] = l_i[mt][1] = 0.f;
        #pragma unroll
        for (int nt = 0; nt < 8; nt++)
            #pragma unroll
            for (int c = 0; c < 4; c++) o[mt][nt][c] = 0.f;
    }

    for (int kt = 0; kt < SEQ / 64; kt++) {
        const bool pf = (kt + 1 < SEQ / 64);
        // Prefetch K(kt+1) into registers (overlaps S-compute).
        if (pf) {
            const size_t kb = base + (size_t)((kt + 1) * 64) * EMB;
            #pragma unroll
            for (int it = 0; it < 8; it++) {
                int idx = tid + it * 128;
                int key = idx & 63, dq = idx >> 6;
                kr[it] = *(const float4*)(Kg + kb + (size_t)key * EMB + dq * 4);
            }
        }

        // ---- S = Q K^T ----
        float s[2][8][4];
        #pragma unroll
        for (int mt = 0; mt < 2; mt++)
            #pragma unroll
            for (int nt = 0; nt < 8; nt++)
                #pragma unroll
                for (int c = 0; c < 4; c++) s[mt][nt][c] = 0.f;

        #pragma unroll
        for (int ks = 0; ks < 8; ks++) {
            const int r0 = ks * 8 + t, r1 = r0 + 4;
            const int sw = (g ^ (t << 1)) << 2;
            uint32_t kb0[8], kb1[8];
            {
                uint4 x = *(const uint4*)(Ks + (r0 << 6) + sw);
                kb0[0] = x.x; kb0[1] = x.y; kb0[2] = x.z; kb0[3] = x.w;
                uint4 y = *(const uint4*)(Ks + (r0 << 6) + sw + 32);
                kb0[4] = y.x; kb0[5] = y.y; kb0[6] = y.z; kb0[7] = y.w;
                uint4 z = *(const uint4*)(Ks + (r1 << 6) + sw);
                kb1[0] = z.x; kb1[1] = z.y; kb1[2] = z.z; kb1[3] = z.w;
                uint4 u = *(const uint4*)(Ks + (r1 << 6) + sw + 32);
                kb1[4] = u.x; kb1[5] = u.y; kb1[6] = u.z; kb1[7] = u.w;
            }
            #pragma unroll
            for (int mt = 0; mt < 2; mt++) {
                const int R = wq + mt * 16;
                uint32_t a[4];
                a[0] = Qs[(R + g)     * QP + ks * 8 + t];
                a[1] = Qs[(R + g + 8) * QP + ks * 8 + t];
                a[2] = Qs[(R + g)     * QP + ks * 8 + t + 4];
                a[3] = Qs[(R + g + 8) * QP + ks * 8 + t + 4];
                #pragma unroll
                for (int nt = 0; nt < 8; nt++)
                    mma_tf32(s[mt][nt], a, kb0[nt], kb1[nt]);
            }
        }

        // ---- online softmax (exp2 domain); converts s in-place to tf32 bits ----
        #pragma unroll
        for (int mt = 0; mt < 2; mt++) {
            #pragma unroll
            for (int hr = 0; hr < 2; hr++) {
                float rmax = -1e30f;
                #pragma unroll
                for (int nt = 0; nt < 8; nt++)
                    rmax = fmaxf(rmax, fmaxf(s[mt][nt][2 * hr], s[mt][nt][2 * hr + 1]));
                rmax = fmaxf(rmax, __shfl_xor_sync(0xffffffffu, rmax, 1));
                rmax = fmaxf(rmax, __shfl_xor_sync(0xffffffffu, rmax, 2));
                float mnew  = fmaxf(m_i[mt][hr], rmax);
                float alpha = ex2(m_i[mt][hr] - mnew);
                float rsum = 0.f;
                #pragma unroll
                for (int nt = 0; nt < 8; nt++) {
                    float p0 = ex2(s[mt][nt][2 * hr]     - mnew);
                    float p1 = ex2(s[mt][nt][2 * hr + 1] - mnew);
                    rsum += p0 + p1;
                    s[mt][nt][2 * hr]     = __uint_as_float(f2tf(p0));
                    s[mt][nt][2 * hr + 1] = __uint_as_float(f2tf(p1));
                }
                rsum += __shfl_xor_sync(0xffffffffu, rsum, 1);
                rsum += __shfl_xor_sync(0xffffffffu, rsum, 2);
                l_i[mt][hr] = l_i[mt][hr] * alpha + rsum;
                m_i[mt][hr] = mnew;
                #pragma unroll
                for (int nt = 0; nt < 8; nt++) {
                    o[mt][nt][2 * hr]     *= alpha;
                    o[mt][nt][2 * hr + 1] *= alpha;
                }
            }
        }

        __syncthreads();   // all warps done reading Ks(kt)

        // Store prefetched K(kt+1); prefetch V(kt+1) (overlaps PV).
        if (pf) {
            #pragma unroll
            for (int it = 0; it < 8; it++) {
                int idx = tid + it * 128;
                int key = idx & 63, dq = idx >> 6;
                Ks[kvw(dq * 4 + 0, key)] = f2tf(kr[it].x);
                Ks[kvw(dq * 4 + 1, key)] = f2tf(kr[it].y);
                Ks[kvw(dq * 4 + 2, key)] = f2tf(kr[it].z);
                Ks[kvw(dq * 4 + 3, key)] = f2tf(kr[it].w);
            }
            const size_t vb = base + (size_t)((kt + 1) * 64) * EMB;
            #pragma unroll
            for (int it = 0; it < 8; it++) {
                int idx = tid + it * 128;
                int key = idx >> 4, dq = idx & 15;
                vr[it] = *(const float4*)(Vg + vb + (size_t)key * EMB + dq * 4);
            }
        }

        // ---- O += P V (P a-frags via warp shuffle of s) ----
        const int srcA = (lane & ~3) | (t >> 1);   // 4g + t/2
        const int srcB = srcA + 2;
        const bool odd = (t & 1);
        #pragma unroll
        for (int ks = 0; ks < 8; ks++) {
            const int r0 = ks * 8 + t, r1 = r0 + 4;
            const int sw = (g ^ (t << 1)) << 2;
            uint32_t vb0[8], vb1[8];
            {
                uint4 x = *(const uint4*)(Vs + (r0 << 6) + sw);
                vb0[0] = x.x; vb0[1] = x.y; vb0[2] = x.z; vb0[3] = x.w;
                uint4 y = *(const uint4*)(Vs + (r0 << 6) + sw + 32);
                vb0[4] = y.x; vb0[5] = y.y; vb0[6] = y.z; vb0[7] = y.w;
                uint4 z = *(const uint4*)(Vs + (r1 << 6) + sw);
                vb1[0] = z.x; vb1[1] = z.y; vb1[2] = z.z; vb1[3] = z.w;
                uint4 u = *(const uint4*)(Vs + (r1 << 6) + sw + 32);
                vb1[4] = u.x; vb1[5] = u.y; vb1[6] = u.z; vb1[7] = u.w;
            }
            #pragma unroll
            for (int mt = 0; mt < 2; mt++) {
                float w0 = __shfl_sync(0xffffffffu, s[mt][ks][0], srcA);
                float w1 = __shfl_sync(0xffffffffu, s[mt][ks][1], srcA);
                float w2 = __shfl_sync(0xffffffffu, s[mt][ks][2], srcA);
                float w3 = __shfl_sync(0xffffffffu, s[mt][ks][3], srcA);
                float x0 = __shfl_sync(0xffffffffu, s[mt][ks][0], srcB);
                float x1 = __shfl_sync(0xffffffffu, s[mt][ks][1], srcB);
                float x2 = __shfl_sync(0xffffffffu, s[mt][ks][2], srcB);
                float x3 = __shfl_sync(0xffffffffu, s[mt][ks][3], srcB);
                uint32_t a[4];
                a[0] = __float_as_uint(odd ? w1 : w0);
                a[1] = __float_as_uint(odd ? w3 : w2);
                a[2] = __float_as_uint(odd ? x1 : x0);
                a[3] = __float_as_uint(odd ? x3 : x2);
                #pragma unroll
                for (int nt = 0; nt < 8; nt++)
                    mma_tf32(o[mt][nt], a, vb0[nt], vb1[nt]);
            }
        }

        __syncthreads();   // all warps done reading Vs(kt)

        if (pf) {
            #pragma unroll
            for (int it = 0; it < 8; it++) {
                int idx = tid + it * 128;
                int key = idx >> 4, dq = idx & 15;
                Vs[kvw(key, dq * 4 + 0)] = f2tf(vr[it].x);
                Vs[kvw(key, dq * 4 + 1)] = f2tf(vr[it].y);
                Vs[kvw(key, dq * 4 + 2)] = f2tf(vr[it].z);
                Vs[kvw(key, dq * 4 + 3)] = f2tf(vr[it].w);
            }
        }
        // V(kt+1) STS is ordered before PV(kt+1) by the next iteration's
        // first __syncthreads(); K(kt+1) STS before S(kt+1) by the second.
    }

    // Normalize + write context in [B, S, H*Dh] layout.
    #pragma unroll
    for (int mt = 0; mt < 2; mt++) {
        float inv0 = __fdividef(1.f, l_i[mt][0]);
        float inv1 = __fdividef(1.f, l_i[mt][1]);
        const int R = q0 + wq + mt * 16;
        #pragma unroll
        for (int nt = 0; nt < 8; nt++) {
            size_t r0 = base + (size_t)(R + g) * EMB + nt * 8 + 2 * t;
            *(float2*)(Og + r0) = make_float2(o[mt][nt][0] * inv0, o[mt][nt][1] * inv0);
            size_t r1 = base + (size_t)(R + g + 8) * EMB + nt * 8 + 2 * t;
            *(float2*)(Og + r1) = make_float2(o[mt][nt][2] * inv1, o[mt][nt][3] * inv1);
        }
    }
}

// ---------------------------------------------------------------------------
extern "C" void kernel_launch(void* const* d_in, const int* in_sizes, int n_in,
                              void* d_out, int out_size)
{
    const float* q  = (const float*)d_in[0];
    const float* k  = (const float*)d_in[1];
    const float* v  = (const float*)d_in[2];
    const float* wq = (const float*)d_in[3];
    const float* bq = (const float*)d_in[4];
    const float* wk = (const float*)d_in[5];
    const float* bk = (const float*)d_in[6];
    const float* wv = (const float*)d_in[7];
    const float* bv = (const float*)d_in[8];
    const float* wo = (const float*)d_in[9];
    const float* bo = (const float*)d_in[10];
    float* out = (float*)d_out;

    float *Qb, *Kb, *Vb, *Cb;
    cudaGetSymbolAddress((void**)&Qb, g_Q);
    cudaGetSymbolAddress((void**)&Kb, g_K);
    cudaGetSymbolAddress((void**)&Vb, g_V);
    cudaGetSymbolAddress((void**)&Cb, g_C);

    // QKV projections: [8192,768] @ [768,512] + bias
    dim3 gp(EMB / 128, MROWS / 128);
    gemm_tf32<<<gp, 256>>>(q, wq, bq, Qb, MROWS, EMB, DIMI);
    gemm_tf32<<<gp, 256>>>(k, wk, bk, Kb, MROWS, EMB, DIMI);
    gemm_tf32<<<gp, 256>>>(v, wv, bv, Vb, MROWS, EMB, DIMI);

    // Flash attention: grid (S/128, B*H)
    int smem = (128 * QP + 64 * 64 * 2) * (int)sizeof(uint32_t);  // 67584 B
    cudaFuncSetAttribute(flash_tf32, cudaFuncAttributeMaxDynamicSharedMemorySize, smem);
    flash_tf32<<<dim3(SEQ / 128, BATCH * HEADS), 128, smem>>>(Qb, Kb, Vb, Cb);

    // Output projection: [8192,512] @ [512,768] + bias -> d_out
    dim3 go(DIMI / 128, MROWS / 128);
    gemm_tf32<<<go, 256>>>(Cb, wo, bo, out, MROWS, DIMI, EMB);
}